// round 16
// baseline (speedup 1.0000x reference)
#include <cuda_runtime.h>
#include <cuda_bf16.h>
#include <math.h>
#include <stdint.h>

#define HC 128
#define NVMAX 50000
#define NEMAX 400000
#define NG 512
#define LAYERS 2
#define NW 24
#define MAXSTEP 6

// packed weight image: [n][k] bf16, row stride 136 (pad 8)
#define WROW 136
#define WIMG_ELEMS (128 * WROW)            // 17408 bf16 per image
#define WIMG_BYTES (WIMG_ELEMS * 2)        // 34816 B
#define AIMG_BYTES (64 * WROW * 2)         // 17408 B, 64-row bf16 tile

// ---------------- scratch (device globals; no allocation) ----------------
__device__ float g_xs0[NVMAX * HC];
__device__ float g_xs1[NVMAX * HC];
__device__ float g_tmp[NVMAX * HC];
__device__ __align__(16) __nv_bfloat16 g_kt0[NVMAX * HC];
__device__ __align__(16) __nv_bfloat16 g_vt0[NVMAX * HC];
__device__ __align__(16) __nv_bfloat16 g_kt1[NVMAX * HC];
__device__ __align__(16) __nv_bfloat16 g_vt1[NVMAX * HC];
__device__ __align__(16) __nv_bfloat16 g_qe0[NVMAX * HC];  // Q of con nodes
__device__ __align__(16) __nv_bfloat16 g_qe1[NVMAX * HC];  // Q of var nodes
__device__ __align__(16) __nv_bfloat16 g_aggv[NVMAX * HC];
__device__ __align__(16) __nv_bfloat16 g_aggc[NVMAX * HC];
__device__ __align__(16) __nv_bfloat16 g_wimg[NW * WIMG_ELEMS];
__device__ float g_bcomp[8 * HC];
__device__ float g_gsum[NG * 2];
__device__ float g_gcnt[NG];
// CSR scratch (seg0: dst=con, seg1: dst=var)
__device__ int g_cnt0[NVMAX], g_cnt1[NVMAX];
__device__ int g_rp0[NVMAX + 1], g_rp1[NVMAX + 1];
__device__ int g_of0[NVMAX + 1], g_of1[NVMAX + 1];
__device__ int g_ss0[NEMAX], g_ss1[NEMAX];
__device__ int g_bs0[64], g_bs1[64];

// ---------------- helpers ----------------
__device__ __forceinline__ uint32_t smem_u32(const void* p) {
    uint32_t a;
    asm("{ .reg .u64 t; cvta.to.shared.u64 t, %1; cvt.u32.u64 %0, t; }" : "=r"(a) : "l"(p));
    return a;
}
__device__ __forceinline__ float gelu_exact(float x) {
    return 0.5f * x * (1.f + erff(x * 0.70710678118654752440f));
}
__device__ __forceinline__ void ldm_x4(uint32_t* r, uint32_t addr) {
    asm volatile("ldmatrix.sync.aligned.m8n8.x4.shared.b16 {%0,%1,%2,%3}, [%4];"
                 : "=r"(r[0]), "=r"(r[1]), "=r"(r[2]), "=r"(r[3]) : "r"(addr));
}
__device__ __forceinline__ void mma16816(float* c, const uint32_t* a, const uint32_t* b) {
    asm volatile("mma.sync.aligned.m16n8k16.row.col.f32.bf16.bf16.f32 "
                 "{%0,%1,%2,%3}, {%4,%5,%6,%7}, {%8,%9}, {%0,%1,%2,%3};"
                 : "+f"(c[0]), "+f"(c[1]), "+f"(c[2]), "+f"(c[3])
                 : "r"(a[0]), "r"(a[1]), "r"(a[2]), "r"(a[3]), "r"(b[0]), "r"(b[1]));
}
__device__ __forceinline__ void cp_async16(uint32_t saddr, const void* gaddr) {
    asm volatile("cp.async.cg.shared.global [%0], [%1], 16;" :: "r"(saddr), "l"(gaddr));
}

// ---------------- weight pre-pack (bf16 image) ----------------
struct PackJobs {
    const float* w[NW];
    const float* rel[NW];
    const float* bin[NW];
    float* bout[NW];
};

__global__ void pack_kernel(PackJobs jobs, __nv_bfloat16* img) {
    int j = blockIdx.x;
    int part = blockIdx.y;
    int tid = threadIdx.x;
    const float* w = jobs.w[j];
    const float* rel = jobs.rel[j];
    __shared__ float rs[4096];
    if (rel) {
        for (int i = tid; i < 4096; i += 256) rs[i] = rel[i];
        __syncthreads();
    }
    __nv_bfloat16* ih = img + (size_t)j * WIMG_ELEMS;
    for (int idx = part * 4096 + tid; idx < (part + 1) * 4096; idx += 256) {
        int k = idx >> 7, n = idx & 127;
        float val;
        if (rel) {
            int h = n >> 5, nn = n & 31;
            const float* wr = w + k * 128 + h * 32;
            const float* rr = rs + h * 1024 + nn;
            float s = 0.f;
#pragma unroll
            for (int jj = 0; jj < 32; jj++) s += wr[jj] * rr[jj * 32];
            val = s;
        } else {
            val = w[k * 128 + n];
        }
        ih[n * WROW + k] = __float2bfloat16(val);
    }
    if (part == 0 && rel && jobs.bout[j] && tid < 128) {
        int h = tid >> 5, nn = tid & 31;
        const float* b = jobs.bin[j];
        float s = 0.f;
#pragma unroll
        for (int jj = 0; jj < 32; jj++) s += b[h * 32 + jj] * rs[h * 1024 + jj * 32 + nn];
        jobs.bout[j][tid] = s;
    }
}

// ---------------- shared GEMM pieces ----------------
#define SM_A 0
#define SM_W0 AIMG_BYTES                    // 17408
#define SM_W1 (AIMG_BYTES + WIMG_BYTES)     // 52224
#define SMEM_MM (AIMG_BYTES + 2 * WIMG_BYTES)   // 87040

// convert 64-row A tile -> smem bf16; A fp32 or bf16; runtime gelu flag
__device__ __forceinline__ void convert_A64(const void* __restrict__ A, int a_bf16,
                                            int row0, int N, char* smem, int tid, int gelu) {
#pragma unroll
    for (int it = 0; it < 8; ++it) {
        int i = tid + it * 256;
        int r = i >> 5;
        int k = (i & 31) * 4;
        int row = row0 + r;
        float4 av = make_float4(0.f, 0.f, 0.f, 0.f);
        if (row < N) {
            if (a_bf16) {
                uint2 raw = *(const uint2*)((const __nv_bfloat16*)A + (size_t)row * HC + k);
                float2 a01 = __bfloat1622float2(*(__nv_bfloat162*)&raw.x);
                float2 a23 = __bfloat1622float2(*(__nv_bfloat162*)&raw.y);
                av = make_float4(a01.x, a01.y, a23.x, a23.y);
            } else {
                av = *(const float4*)((const float*)A + (size_t)row * HC + k);
            }
        }
        if (gelu) {
            av.x = gelu_exact(av.x); av.y = gelu_exact(av.y);
            av.z = gelu_exact(av.z); av.w = gelu_exact(av.w);
        }
        __nv_bfloat162 h01 = __float22bfloat162_rn(make_float2(av.x, av.y));
        __nv_bfloat162 h23 = __float22bfloat162_rn(make_float2(av.z, av.w));
        uint32_t off = (uint32_t)(r * WROW + k) * 2;
        *(uint2*)(smem + SM_A + off) = make_uint2(*(uint32_t*)&h01, *(uint32_t*)&h23);
    }
}

// load one 34816-B W image asynchronously (2176 float4)
__device__ __forceinline__ void load_W_async(uint32_t sdst, const __nv_bfloat16* Wimg, int tid) {
#pragma unroll
    for (int j = 0; j < 9; j++) {
        int i = tid + j * 256;
        if (i < 2176) cp_async16(sdst + i * 16, (const float4*)Wimg + i);
    }
    asm volatile("cp.async.commit_group;" ::: "memory");
}

// 1-pass bf16 GEMM
__device__ __forceinline__ void mma_tile1(uint32_t a_lane, uint32_t b_lane, float acc[2][4][4]) {
#pragma unroll
    for (int i = 0; i < 2; i++)
#pragma unroll
        for (int j = 0; j < 4; j++)
#pragma unroll
            for (int q = 0; q < 4; q++) acc[i][j][q] = 0.f;
#pragma unroll
    for (int ks = 0; ks < 8; ks++) {
        uint32_t ar[2][4], br[2][4];
        ldm_x4(ar[0], a_lane + ks * 32);
        ldm_x4(ar[1], a_lane + ks * 32 + 16 * WROW * 2);
        ldm_x4(br[0], b_lane + ks * 32);
        ldm_x4(br[1], b_lane + ks * 32 + 16 * WROW * 2);
#pragma unroll
        for (int mt = 0; mt < 2; mt++) {
            mma16816(acc[mt][0], ar[mt], br[0] + 0);
            mma16816(acc[mt][1], ar[mt], br[0] + 2);
            mma16816(acc[mt][2], ar[mt], br[1] + 0);
            mma16816(acc[mt][3], ar[mt], br[1] + 2);
        }
    }
}

// ---------------- mega-chain GEMM kernel (1..6 steps, double-buffered W) -----
struct ChainP {
    const void* A;
    const float* xprev;
    const __nv_bfloat16* W[MAXSTEP];
    const float* bias[MAXSTEP];
    void* Cg[MAXSTEP];
    const float* gate[MAXSTEP];
    int relu[MAXSTEP];
    int half_out[MAXSTEP];
    int chain[MAXSTEP];
    int gelu_in;
    int a_bf16;
    int nsteps;
    int N;
};

__global__ void __launch_bounds__(256, 2)
chain_kernel(ChainP P) {
    extern __shared__ char smem[];
    int tid = threadIdx.x;
    int wid = tid >> 5;
    int lane = tid & 31;
    int row0 = blockIdx.x * 64;
    uint32_t sb = smem_u32(smem);

    load_W_async(sb + SM_W0, P.W[0], tid);
    convert_A64(P.A, P.a_bf16, row0, P.N, smem, tid, P.gelu_in);
    asm volatile("cp.async.wait_group 0;" ::: "memory");
    __syncthreads();
    if (P.nsteps > 1) load_W_async(sb + SM_W1, P.W[1], tid);

    int warpM = wid >> 2;
    int warpN = wid & 3;
    uint32_t a_lane = sb + SM_A +
        ((uint32_t)((warpM * 32 + (lane & 15)) * WROW + ((lane >> 4) << 3)) << 1);
    uint32_t b_lane0 = sb + SM_W0 +
        ((uint32_t)((warpN * 32 + (lane & 7) + ((lane >> 4) << 3)) * WROW +
                    (((lane >> 3) & 1) << 3)) << 1);
    int gid = lane >> 2, tq = lane & 3;

    for (int s = 0; s < P.nsteps; s++) {
        float acc[2][4][4];
        mma_tile1(a_lane, b_lane0 + (uint32_t)(s & 1) * WIMG_BYTES, acc);
        bool last = (s + 1 == P.nsteps);
        __syncthreads();                 // all warps done reading W[s] and A
        bool more2 = (s + 2 < P.nsteps);
        if (more2) load_W_async(sb + SM_W0 + (uint32_t)(s & 1) * WIMG_BYTES, P.W[s + 2], tid);

        const float* bias = P.bias[s];
        void* Cg = P.Cg[s];
        const float* gp = P.gate[s];
        int rl = P.relu[s];
        int ho = P.half_out[s];
        int ch = P.chain[s];
        float g = 0.f, og = 0.f;
        if (gp) { g = 1.f / (1.f + expf(-*gp)); og = 1.f - g; }
#pragma unroll
        for (int mt = 0; mt < 2; mt++) {
#pragma unroll
            for (int nt = 0; nt < 4; nt++) {
                int col = warpN * 32 + nt * 8 + tq * 2;
                float2 bv = *(const float2*)(bias + col);
#pragma unroll
                for (int half = 0; half < 2; half++) {
                    int rloc = warpM * 32 + mt * 16 + gid + half * 8;
                    int row = row0 + rloc;
                    float c0 = acc[mt][nt][half * 2 + 0] + bv.x;
                    float c1 = acc[mt][nt][half * 2 + 1] + bv.y;
                    if (rl) { c0 = fmaxf(c0, 0.f); c1 = fmaxf(c1, 0.f); }
                    if (gp && row < P.N) {
                        float2 xp = *(const float2*)(P.xprev + (size_t)row * HC + col);
                        c0 = g * c0 + og * xp.x;
                        c1 = g * c1 + og * xp.y;
                    }
                    if (Cg && row < P.N) {
                        if (ho) {
                            __nv_bfloat162 h2 = __float22bfloat162_rn(make_float2(c0, c1));
                            *(uint32_t*)((__nv_bfloat16*)Cg + (size_t)row * HC + col) =
                                *(uint32_t*)&h2;
                        } else {
                            *(float2*)((float*)Cg + (size_t)row * HC + col) =
                                make_float2(c0, c1);
                        }
                    }
                    if (ch) {
                        __nv_bfloat162 h2 = __float22bfloat162_rn(make_float2(c0, c1));
                        uint32_t off = (uint32_t)(rloc * WROW + col) * 2;
                        *(uint32_t*)(smem + SM_A + off) = *(uint32_t*)&h2;
                    }
                }
            }
        }
        if (!last) {
            if (more2)
                asm volatile("cp.async.wait_group 1;" ::: "memory");  // W[s+1] done
            else
                asm volatile("cp.async.wait_group 0;" ::: "memory");
            __syncthreads();             // W[s+1] + chained A stores visible
        }
    }
}

// ---------------- CSR build ----------------
__global__ void clear_cnt_kernel(int* c0, int n0, int* c1, int n1) {
    int i = blockIdx.x * blockDim.x + threadIdx.x;
    if (i < n0) c0[i] = 0;
    if (i < n1) c1[i] = 0;
}

__global__ void hist_kernel(const int* d0, int E0, int* c0,
                            const int* d1, int E1, int* c1) {
    int e = blockIdx.x * blockDim.x + threadIdx.x;
    if (e < E0) atomicAdd(&c0[d0[e]], 1);
    if (e < E1) atomicAdd(&c1[d1[e]], 1);
}

__global__ void scan_p1_kernel(const int* c0, int n0, int* rp0, int* of0, int* bs0,
                               const int* c1, int n1, int* rp1, int* of1, int* bs1) {
    int seg = blockIdx.y;
    const int* cnt = seg ? c1 : c0;
    int n = seg ? n1 : n0;
    int* rp = seg ? rp1 : rp0;
    int* of = seg ? of1 : of0;
    int* bs = seg ? bs1 : bs0;
    int tid = threadIdx.x;
    int i = blockIdx.x * 1024 + tid;
    int v = (i < n) ? cnt[i] : 0;
    int lane = tid & 31, wd = tid >> 5;
    int x = v;
#pragma unroll
    for (int off = 1; off < 32; off <<= 1) {
        int t = __shfl_up_sync(0xffffffffu, x, off);
        if (lane >= off) x += t;
    }
    __shared__ int ws[32];
    if (lane == 31) ws[wd] = x;
    __syncthreads();
    if (wd == 0) {
        int w = ws[lane];
#pragma unroll
        for (int off = 1; off < 32; off <<= 1) {
            int t = __shfl_up_sync(0xffffffffu, w, off);
            if (lane >= off) w += t;
        }
        ws[lane] = w;
    }
    __syncthreads();
    int incl = x + (wd > 0 ? ws[wd - 1] : 0);
    if (i < n) { rp[i + 1] = incl; of[i + 1] = incl; }
    if (tid == 1023) bs[blockIdx.x] = incl;
    if (i == 0) { rp[0] = 0; of[0] = 0; }
}

__global__ void scan_p2_kernel(int* rp0, int* of0, const int* bs0, int n0,
                               int* rp1, int* of1, const int* bs1, int n1) {
    int seg = blockIdx.y;
    int* rp = seg ? rp1 : rp0;
    int* of = seg ? of1 : of0;
    const int* bs = seg ? bs1 : bs0;
    int n = seg ? n1 : n0;
    int bid = blockIdx.x;
    if (bid == 0) return;
    __shared__ int soff;
    if (threadIdx.x < 32) {
        int acc = 0;
        for (int j = threadIdx.x; j < bid; j += 32) acc += bs[j];
#pragma unroll
        for (int o = 16; o; o >>= 1) acc += __shfl_xor_sync(0xffffffffu, acc, o);
        if (threadIdx.x == 0) soff = acc;
    }
    __syncthreads();
    int i = bid * 1024 + threadIdx.x;
    if (i < n) { rp[i + 1] += soff; of[i + 1] += soff; }
}

__global__ void scatter_kernel(const int* s0, const int* d0, int E0, int* o0, int* ss0,
                               const int* s1, const int* d1, int E1, int* o1, int* ss1) {
    int e = blockIdx.x * blockDim.x + threadIdx.x;
    if (e < E0) { int p = atomicAdd(&o0[d0[e]], 1); ss0[p] = s0[e]; }
    if (e < E1) { int p = atomicAdd(&o1[d1[e]], 1); ss1[p] = s1[e]; }
}

// ---------------- CSR attention: warp per dst, all-bf16, 2-edge unroll -------
struct CsrP {
    const __nv_bfloat16* q[2];
    const __nv_bfloat16* kt[2];
    const __nv_bfloat16* vt[2];
    const int* rowptr[2];
    const int* ssrc[2];
    const float* prel[2];
    __nv_bfloat16* agg[2];
    int Nd0, Ndtot;
};

__global__ void attn_csr_kernel(CsrP P) {
    int w = blockIdx.x * 8 + (threadIdx.x >> 5);
    if (w >= P.Ndtot) return;
    int seg = w >= P.Nd0;
    int d = w - (seg ? P.Nd0 : 0);
    int lane = threadIdx.x & 31;
    int h = lane >> 3;
    const int* rp = P.rowptr[seg];
    int beg = rp[d], end = rp[d + 1];
    float pr = P.prel[seg][h] * 0.17677669529663687f;
    float4 qv;
    {
        uint2 qraw = *(const uint2*)(P.q[seg] + (size_t)d * HC + lane * 4);
        float2 qa = __bfloat1622float2(*(__nv_bfloat162*)&qraw.x);
        float2 qb = __bfloat1622float2(*(__nv_bfloat162*)&qraw.y);
        qv = make_float4(qa.x, qa.y, qb.x, qb.y);
    }
    const __nv_bfloat16* kt = P.kt[seg];
    const __nv_bfloat16* vt = P.vt[seg];
    const int* ss = P.ssrc[seg];
    float4 acc = make_float4(0.f, 0.f, 0.f, 0.f);
    float den = 0.f;
    int i = beg;
    for (; i + 1 < end; i += 2) {
        int s0 = ss[i], s1 = ss[i + 1];
        uint2 k0 = *(const uint2*)(kt + (size_t)s0 * HC + lane * 4);
        uint2 v0 = *(const uint2*)(vt + (size_t)s0 * HC + lane * 4);
        uint2 k1 = *(const uint2*)(kt + (size_t)s1 * HC + lane * 4);
        uint2 v1 = *(const uint2*)(vt + (size_t)s1 * HC + lane * 4);
        float2 k0a = __bfloat1622float2(*(__nv_bfloat162*)&k0.x);
        float2 k0b = __bfloat1622float2(*(__nv_bfloat162*)&k0.y);
        float2 k1a = __bfloat1622float2(*(__nv_bfloat162*)&k1.x);
        float2 k1b = __bfloat1622float2(*(__nv_bfloat162*)&k1.y);
        float p0 = qv.x * k0a.x + qv.y * k0a.y + qv.z * k0b.x + qv.w * k0b.y;
        float p1 = qv.x * k1a.x + qv.y * k1a.y + qv.z * k1b.x + qv.w * k1b.y;
        p0 += __shfl_xor_sync(0xffffffffu, p0, 1);
        p1 += __shfl_xor_sync(0xffffffffu, p1, 1);
        p0 += __shfl_xor_sync(0xffffffffu, p0, 2);
        p1 += __shfl_xor_sync(0xffffffffu, p1, 2);
        p0 += __shfl_xor_sync(0xffffffffu, p0, 4);
        p1 += __shfl_xor_sync(0xffffffffu, p1, 4);
        float ex0 = expf(p0 * pr);
        float ex1 = expf(p1 * pr);
        den += ex0;
        den += ex1;
        float2 v0a = __bfloat1622float2(*(__nv_bfloat162*)&v0.x);
        float2 v0b = __bfloat1622float2(*(__nv_bfloat162*)&v0.y);
        float2 v1a = __bfloat1622float2(*(__nv_bfloat162*)&v1.x);
        float2 v1b = __bfloat1622float2(*(__nv_bfloat162*)&v1.y);
        acc.x += ex0 * v0a.x + ex1 * v1a.x;
        acc.y += ex0 * v0a.y + ex1 * v1a.y;
        acc.z += ex0 * v0b.x + ex1 * v1b.x;
        acc.w += ex0 * v0b.y + ex1 * v1b.y;
    }
    if (i < end) {
        int s = ss[i];
        uint2 kraw = *(const uint2*)(kt + (size_t)s * HC + lane * 4);
        uint2 vraw = *(const uint2*)(vt + (size_t)s * HC + lane * 4);
        float2 ka = __bfloat1622float2(*(__nv_bfloat162*)&kraw.x);
        float2 kb = __bfloat1622float2(*(__nv_bfloat162*)&kraw.y);
        float2 va = __bfloat1622float2(*(__nv_bfloat162*)&vraw.x);
        float2 vb = __bfloat1622float2(*(__nv_bfloat162*)&vraw.y);
        float p = qv.x * ka.x + qv.y * ka.y + qv.z * kb.x + qv.w * kb.y;
        p += __shfl_xor_sync(0xffffffffu, p, 1);
        p += __shfl_xor_sync(0xffffffffu, p, 2);
        p += __shfl_xor_sync(0xffffffffu, p, 4);
        float ex = expf(p * pr);
        den += ex;
        acc.x += ex * va.x; acc.y += ex * va.y;
        acc.z += ex * vb.x; acc.w += ex * vb.y;
    }
    float rcp = (den > 0.f) ? 1.f / den : 0.f;
    __nv_bfloat162 o01 = __float22bfloat162_rn(make_float2(acc.x * rcp, acc.y * rcp));
    __nv_bfloat162 o23 = __float22bfloat162_rn(make_float2(acc.z * rcp, acc.w * rcp));
    *(uint2*)(P.agg[seg] + (size_t)d * HC + lane * 4) =
        make_uint2(*(uint32_t*)&o01, *(uint32_t*)&o23);
}

// ---------------- output head ----------------
__global__ void head_clear_kernel(float* __restrict__ gsum, float* __restrict__ gcnt) {
    int i = blockIdx.x * blockDim.x + threadIdx.x;
    if (i < NG * 2) gsum[i] = 0.f;
    if (i < NG) gcnt[i] = 0.f;
}

__global__ void out_head_kernel(const float* __restrict__ X, const float* __restrict__ W2,
                                const float* __restrict__ b2, const int* __restrict__ batch,
                                float* __restrict__ gsum, float* __restrict__ gcnt, int N) {
    int n = blockIdx.x * 8 + (threadIdx.x >> 5);
    if (n >= N) return;
    int lane = threadIdx.x & 31;
    float4 x = *(const float4*)(X + (size_t)n * HC + lane * 4);
    float4 wa = *(const float4*)(W2 + lane * 8);
    float4 wb = *(const float4*)(W2 + lane * 8 + 4);
    float p0 = x.x * wa.x + x.y * wa.z + x.z * wb.x + x.w * wb.z;
    float p1 = x.x * wa.y + x.y * wa.w + x.z * wb.y + x.w * wb.w;
#pragma unroll
    for (int off = 16; off > 0; off >>= 1) {
        p0 += __shfl_xor_sync(0xffffffffu, p0, off);
        p1 += __shfl_xor_sync(0xffffffffu, p1, off);
    }
    if (lane == 0) {
        float l0 = p0 + b2[0], l1 = p1 + b2[1];
        float m = fmaxf(l0, l1);
        float e0 = expf(l0 - m), e1 = expf(l1 - m);
        float inv = 1.f / (e0 + e1);
        int g = batch[n];
        atomicAdd(&gsum[g * 2 + 0], e0 * inv);
        atomicAdd(&gsum[g * 2 + 1], e1 * inv);
        atomicAdd(&gcnt[g], 1.f);
    }
}

__global__ void finalize_kernel(const float* __restrict__ gsum, const float* __restrict__ gcnt,
                                float* __restrict__ out, int G) {
    int g = blockIdx.x * blockDim.x + threadIdx.x;
    if (g >= G) return;
    float c = fmaxf(gcnt[g], 1.f);
    out[g * 2 + 0] = gsum[g * 2 + 0] / c;
    out[g * 2 + 1] = gsum[g * 2 + 1] / c;
}

// ---------------- host orchestration ----------------
extern "C" void kernel_launch(void* const* d_in, const int* in_sizes, int n_in,
                              void* d_out, int out_size) {
    const float* x_var = (const float*)d_in[0];
    const float* x_con = (const float*)d_in[1];
    const float* mlp_in_w = (const float*)d_in[2];
    const float* mlp_in_b = (const float*)d_in[3];
    const float* w0 = (const float*)d_in[4];
    const float* b0 = (const float*)d_in[5];
    const float* w1 = (const float*)d_in[6];
    const float* b1 = (const float*)d_in[7];
    const float* w2 = (const float*)d_in[8];
    const float* b2 = (const float*)d_in[9];
    const float* k_w = (const float*)d_in[10];
    const float* k_b = (const float*)d_in[11];
    const float* q_w = (const float*)d_in[12];
    const float* q_b = (const float*)d_in[13];
    const float* v_w = (const float*)d_in[14];
    const float* v_b = (const float*)d_in[15];
    const float* a_w = (const float*)d_in[16];
    const float* a_b = (const float*)d_in[17];
    const float* skip = (const float*)d_in[18];
    const float* a_rel = (const float*)d_in[19];
    const float* m_rel = (const float*)d_in[20];
    const float* p_rel = (const float*)d_in[21];
    const int* evc = (const int*)d_in[22];
    const int* ecv = (const int*)d_in[23];
    const int* batch = (const int*)d_in[24];
    float* out = (float*)d_out;

    int Nv = in_sizes[0] / HC;
    int Nc = in_sizes[1] / HC;
    int Evc = in_sizes[22] / 2;
    int Ecv = in_sizes[23] / 2;

    float *xs0, *xs1, *tmp, *bcomp, *gsum, *gcnt;
    __nv_bfloat16 *kt0, *vt0, *kt1, *vt1, *qe0, *qe1, *aggv, *aggc;
    int *cnt0, *cnt1, *rp0, *rp1, *of0, *of1, *ss0, *ss1, *bs0, *bs1;
    __nv_bfloat16* wimg;
    cudaGetSymbolAddress((void**)&xs0, g_xs0);
    cudaGetSymbolAddress((void**)&xs1, g_xs1);
    cudaGetSymbolAddress((void**)&tmp, g_tmp);
    cudaGetSymbolAddress((void**)&kt0, g_kt0);
    cudaGetSymbolAddress((void**)&vt0, g_vt0);
    cudaGetSymbolAddress((void**)&kt1, g_kt1);
    cudaGetSymbolAddress((void**)&vt1, g_vt1);
    cudaGetSymbolAddress((void**)&qe0, g_qe0);
    cudaGetSymbolAddress((void**)&qe1, g_qe1);
    cudaGetSymbolAddress((void**)&aggv, g_aggv);
    cudaGetSymbolAddress((void**)&aggc, g_aggc);
    cudaGetSymbolAddress((void**)&wimg, g_wimg);
    cudaGetSymbolAddress((void**)&bcomp, g_bcomp);
    cudaGetSymbolAddress((void**)&gsum, g_gsum);
    cudaGetSymbolAddress((void**)&gcnt, g_gcnt);
    cudaGetSymbolAddress((void**)&cnt0, g_cnt0);
    cudaGetSymbolAddress((void**)&cnt1, g_cnt1);
    cudaGetSymbolAddress((void**)&rp0, g_rp0);
    cudaGetSymbolAddress((void**)&rp1, g_rp1);
    cudaGetSymbolAddress((void**)&of0, g_of0);
    cudaGetSymbolAddress((void**)&of1, g_of1);
    cudaGetSymbolAddress((void**)&ss0, g_ss0);
    cudaGetSymbolAddress((void**)&ss1, g_ss1);
    cudaGetSymbolAddress((void**)&bs0, g_bs0);
    cudaGetSymbolAddress((void**)&bs1, g_bs1);

    cudaFuncSetAttribute(chain_kernel, cudaFuncAttributeMaxDynamicSharedMemorySize, SMEM_MM);

    // ---- weight packing ----
    PackJobs pj;
    for (int j = 0; j < NW; j++) { pj.w[j] = nullptr; pj.rel[j] = nullptr; pj.bin[j] = nullptr; pj.bout[j] = nullptr; }
    for (int t = 0; t < 2; t++)
        for (int i = 0; i < 3; i++) pj.w[t * 3 + i] = mlp_in_w + (size_t)(t * 3 + i) * 16384;
    for (int li = 0; li < 4; li++) {
        pj.w[6 + li] = k_w + (size_t)li * 16384;
        pj.rel[6 + li] = a_rel + (size_t)li * 4096;
        pj.bin[6 + li] = k_b + (size_t)li * 128;
        pj.bout[6 + li] = bcomp + (size_t)li * 128;
        pj.w[10 + li] = v_w + (size_t)li * 16384;
        pj.rel[10 + li] = m_rel + (size_t)li * 4096;
        pj.bin[10 + li] = v_b + (size_t)li * 128;
        pj.bout[10 + li] = bcomp + (size_t)(4 + li) * 128;
        pj.w[14 + li] = q_w + (size_t)li * 16384;
        pj.w[18 + li] = a_w + (size_t)li * 16384;
    }
    pj.w[22] = w0;
    pj.w[23] = w1;
    pack_kernel<<<dim3(NW, 4), 256>>>(pj, wimg);

#define IMG(j) (wimg + (size_t)(j) * WIMG_ELEMS)

    // ---- CSR build (seg0: dst=con, seg1: dst=var) ----
    {
        int mx = (Nv > Nc ? Nv : Nc);
        clear_cnt_kernel<<<(mx + 511) / 512, 512>>>(cnt0, Nc, cnt1, Nv);
        int me = (Evc > Ecv ? Evc : Ecv);
        hist_kernel<<<(me + 511) / 512, 512>>>(evc + Evc, Evc, cnt0, ecv + Ecv, Ecv, cnt1);
        int nb = (mx + 1023) / 1024;
        scan_p1_kernel<<<dim3(nb, 2), 1024>>>(cnt0, Nc, rp0, of0, bs0,
                                              cnt1, Nv, rp1, of1, bs1);
        scan_p2_kernel<<<dim3(nb, 2), 1024>>>(rp0, of0, bs0, Nc, rp1, of1, bs1, Nv);
        scatter_kernel<<<(me + 511) / 512, 512>>>(evc, evc + Evc, Evc, of0, ss0,
                                                  ecv, ecv + Ecv, Ecv, of1, ss1);
    }

    auto set_kvq = [&](ChainP& c, int s0, int t, int li) {
        c.W[s0 + 0] = IMG(6 + li);  c.bias[s0 + 0] = bcomp + (size_t)li * 128;
        c.Cg[s0 + 0] = (t == 0) ? (void*)kt0 : (void*)kt1;
        c.half_out[s0 + 0] = 1;
        c.W[s0 + 1] = IMG(10 + li); c.bias[s0 + 1] = bcomp + (size_t)(4 + li) * 128;
        c.Cg[s0 + 1] = (t == 0) ? (void*)vt0 : (void*)vt1;
        c.half_out[s0 + 1] = 1;
        c.W[s0 + 2] = IMG(14 + li); c.bias[s0 + 2] = q_b + (size_t)li * 128;
        c.Cg[s0 + 2] = (t == 0) ? (void*)qe1 : (void*)qe0;
        c.half_out[s0 + 2] = 1;
    };

    // ---- mega chain per type: input MLP x3 -> xs -> K,V,Q (layer 0) ----
    for (int t = 0; t < 2; t++) {
        ChainP c{};
        c.A = (t == 0) ? (const void*)x_var : (const void*)x_con;
        c.N = (t == 0) ? Nv : Nc;
        c.xprev = nullptr;
        c.gelu_in = 0;
        c.a_bf16 = 0;
        c.nsteps = 6;
        for (int i = 0; i < 3; i++) {
            c.W[i] = IMG(t * 3 + i);
            c.bias[i] = mlp_in_b + (size_t)(t * 3 + i) * 128;
            c.relu[i] = (i < 2);
            c.chain[i] = 1;
        }
        c.Cg[2] = (t == 0) ? (void*)xs0 : (void*)xs1;
        set_kvq(c, 3, t, t);
        chain_kernel<<<(c.N + 63) / 64, 256, SMEM_MM>>>(c);
    }

    // ---- layer 0 attention ----
    {
        CsrP cp{};
        cp.q[0] = qe0; cp.kt[0] = kt0; cp.vt[0] = vt0;
        cp.rowptr[0] = rp0; cp.ssrc[0] = ss0;
        cp.prel[0] = p_rel + 0 * 4;
        cp.agg[0] = aggc;
        cp.q[1] = qe1; cp.kt[1] = kt1; cp.vt[1] = vt1;
        cp.rowptr[1] = rp1; cp.ssrc[1] = ss1;
        cp.prel[1] = p_rel + 1 * 4;
        cp.agg[1] = aggv;
        cp.Nd0 = Nc; cp.Ndtot = Nc + Nv;
        attn_csr_kernel<<<(cp.Ndtot + 7) / 8, 256>>>(cp);
    }

    // ---- per type: gated(layer0) -> xs -> K,V,Q (layer 1) ----
    for (int t = 0; t < 2; t++) {
        int li = 0 * 2 + t;
        ChainP c{};
        c.A = (t == 0) ? (const void*)aggv : (const void*)aggc;
        c.N = (t == 0) ? Nv : Nc;
        c.xprev = (t == 0) ? xs0 : xs1;
        c.gelu_in = 1;
        c.a_bf16 = 1;
        c.nsteps = 4;
        c.W[0] = IMG(18 + li); c.bias[0] = a_b + (size_t)li * 128;
        c.gate[0] = skip + li;
        c.Cg[0] = (t == 0) ? (void*)xs0 : (void*)xs1;
        c.chain[0] = 1;
        set_kvq(c, 1, t, 2 + t);
        chain_kernel<<<(c.N + 63) / 64, 256, SMEM_MM>>>(c);
    }

    // ---- layer 1 attention ----
    {
        CsrP cp{};
        cp.q[0] = qe0; cp.kt[0] = kt0; cp.vt[0] = vt0;
        cp.rowptr[0] = rp0; cp.ssrc[0] = ss0;
        cp.prel[0] = p_rel + 2 * 4;
        cp.agg[0] = aggc;
        cp.q[1] = qe1; cp.kt[1] = kt1; cp.vt[1] = vt1;
        cp.rowptr[1] = rp1; cp.ssrc[1] = ss1;
        cp.prel[1] = p_rel + 3 * 4;
        cp.agg[1] = aggv;
        cp.Nd0 = Nc; cp.Ndtot = Nc + Nv;
        attn_csr_kernel<<<(cp.Ndtot + 7) / 8, 256>>>(cp);
    }

    // ---- var: gated(layer1) -> xs0 -> head W0 -> head W1 -> tmp ----
    {
        ChainP c{};
        c.A = (const void*)aggv;
        c.N = Nv;
        c.xprev = xs0;
        c.gelu_in = 1;
        c.a_bf16 = 1;
        c.nsteps = 3;
        c.W[0] = IMG(18 + 2); c.bias[0] = a_b + (size_t)2 * 128;
        c.gate[0] = skip + 2;
        c.Cg[0] = (void*)xs0;
        c.chain[0] = 1;
        c.W[1] = IMG(22); c.bias[1] = b0; c.relu[1] = 1; c.chain[1] = 1;
        c.W[2] = IMG(23); c.bias[2] = b1; c.relu[2] = 1; c.Cg[2] = (void*)tmp;
        chain_kernel<<<(Nv + 63) / 64, 256, SMEM_MM>>>(c);
    }
    // ---- con: gated(layer1) -> xs1 (1 step) ----
    {
        ChainP c{};
        c.A = (const void*)aggc;
        c.N = Nc;
        c.xprev = xs1;
        c.gelu_in = 1;
        c.a_bf16 = 1;
        c.nsteps = 1;
        c.W[0] = IMG(18 + 3); c.bias[0] = a_b + (size_t)3 * 128;
        c.gate[0] = skip + 3;
        c.Cg[0] = (void*)xs1;
        chain_kernel<<<(Nc + 63) / 64, 256, SMEM_MM>>>(c);
    }

    head_clear_kernel<<<(NG * 2 + 255) / 256, 256>>>(gsum, gcnt);
    out_head_kernel<<<(Nv + 7) / 8, 256>>>(tmp, w2, b2, batch, gsum, gcnt, Nv);
    finalize_kernel<<<(NG + 255) / 256, 256>>>(gsum, gcnt, out, NG);
}

// round 17
// speedup vs baseline: 1.0775x; 1.0775x over previous
#include <cuda_runtime.h>
#include <cuda_bf16.h>
#include <math.h>
#include <stdint.h>

#define HC 128
#define NVMAX 50000
#define NEMAX 400000
#define NG 512
#define LAYERS 2
#define NW 24
#define MAXSTEP 6

// packed weight image: [n][k] bf16, row stride 136 (pad 8)
#define WROW 136
#define WIMG_ELEMS (128 * WROW)            // 17408 bf16 per image
#define WIMG_BYTES (WIMG_ELEMS * 2)        // 34816 B
#define AIMG_BYTES (64 * WROW * 2)         // 17408 B, 64-row bf16 tile

// ---------------- scratch (device globals; no allocation) ----------------
__device__ float g_xs0[NVMAX * HC];
__device__ float g_xs1[NVMAX * HC];
__device__ float g_tmp[NVMAX * HC];
__device__ __align__(16) __nv_bfloat16 g_kt0[NVMAX * HC];
__device__ __align__(16) __nv_bfloat16 g_vt0[NVMAX * HC];
__device__ __align__(16) __nv_bfloat16 g_kt1[NVMAX * HC];
__device__ __align__(16) __nv_bfloat16 g_vt1[NVMAX * HC];
__device__ __align__(16) __nv_bfloat16 g_qe0[NVMAX * HC];  // Q of con nodes
__device__ __align__(16) __nv_bfloat16 g_qe1[NVMAX * HC];  // Q of var nodes
__device__ __align__(16) __nv_bfloat16 g_aggv[NVMAX * HC];
__device__ __align__(16) __nv_bfloat16 g_aggc[NVMAX * HC];
__device__ __align__(16) __nv_bfloat16 g_wimg[NW * WIMG_ELEMS];
__device__ float g_bcomp[8 * HC];
__device__ float g_gsum[NG * 2];
__device__ float g_gcnt[NG];
// CSR scratch (seg0: dst=con, seg1: dst=var)
__device__ int g_cnt0[NVMAX], g_cnt1[NVMAX];
__device__ int g_rp0[NVMAX + 1], g_rp1[NVMAX + 1];
__device__ int g_of0[NVMAX + 1], g_of1[NVMAX + 1];
__device__ int g_ss0[NEMAX], g_ss1[NEMAX];
__device__ int g_bs0[64], g_bs1[64];

// ---------------- helpers ----------------
__device__ __forceinline__ uint32_t smem_u32(const void* p) {
    uint32_t a;
    asm("{ .reg .u64 t; cvta.to.shared.u64 t, %1; cvt.u32.u64 %0, t; }" : "=r"(a) : "l"(p));
    return a;
}
__device__ __forceinline__ float gelu_exact(float x) {
    return 0.5f * x * (1.f + erff(x * 0.70710678118654752440f));
}
__device__ __forceinline__ void ldm_x4(uint32_t* r, uint32_t addr) {
    asm volatile("ldmatrix.sync.aligned.m8n8.x4.shared.b16 {%0,%1,%2,%3}, [%4];"
                 : "=r"(r[0]), "=r"(r[1]), "=r"(r[2]), "=r"(r[3]) : "r"(addr));
}
__device__ __forceinline__ void mma16816(float* c, const uint32_t* a, const uint32_t* b) {
    asm volatile("mma.sync.aligned.m16n8k16.row.col.f32.bf16.bf16.f32 "
                 "{%0,%1,%2,%3}, {%4,%5,%6,%7}, {%8,%9}, {%0,%1,%2,%3};"
                 : "+f"(c[0]), "+f"(c[1]), "+f"(c[2]), "+f"(c[3])
                 : "r"(a[0]), "r"(a[1]), "r"(a[2]), "r"(a[3]), "r"(b[0]), "r"(b[1]));
}
__device__ __forceinline__ void cp_async16(uint32_t saddr, const void* gaddr) {
    asm volatile("cp.async.cg.shared.global [%0], [%1], 16;" :: "r"(saddr), "l"(gaddr));
}

// ---------------- weight pre-pack (bf16 image) ----------------
struct PackJobs {
    const float* w[NW];
    const float* rel[NW];
    const float* bin[NW];
    float* bout[NW];
};

__global__ void pack_kernel(PackJobs jobs, __nv_bfloat16* img) {
    int j = blockIdx.x;
    int part = blockIdx.y;
    int tid = threadIdx.x;
    const float* w = jobs.w[j];
    const float* rel = jobs.rel[j];
    __shared__ float rs[4096];
    if (rel) {
        for (int i = tid; i < 4096; i += 256) rs[i] = rel[i];
        __syncthreads();
    }
    __nv_bfloat16* ih = img + (size_t)j * WIMG_ELEMS;
    for (int idx = part * 4096 + tid; idx < (part + 1) * 4096; idx += 256) {
        int k = idx >> 7, n = idx & 127;
        float val;
        if (rel) {
            int h = n >> 5, nn = n & 31;
            const float* wr = w + k * 128 + h * 32;
            const float* rr = rs + h * 1024 + nn;
            float s = 0.f;
#pragma unroll
            for (int jj = 0; jj < 32; jj++) s += wr[jj] * rr[jj * 32];
            val = s;
        } else {
            val = w[k * 128 + n];
        }
        ih[n * WROW + k] = __float2bfloat16(val);
    }
    if (part == 0 && rel && jobs.bout[j] && tid < 128) {
        int h = tid >> 5, nn = tid & 31;
        const float* b = jobs.bin[j];
        float s = 0.f;
#pragma unroll
        for (int jj = 0; jj < 32; jj++) s += b[h * 32 + jj] * rs[h * 1024 + jj * 32 + nn];
        jobs.bout[j][tid] = s;
    }
}

// ---------------- shared GEMM pieces ----------------
#define SM_A 0
#define SM_W0 AIMG_BYTES                    // 17408
#define SM_W1 (AIMG_BYTES + WIMG_BYTES)     // 52224
#define SMEM_MM (AIMG_BYTES + 2 * WIMG_BYTES)   // 87040

// fp32 A convert (round-14 proven path): 4 cols/thread, 16B loads
__device__ __forceinline__ void convert_A64_f32(const float* __restrict__ A,
                                                int row0, int N, char* smem, int tid, int gelu) {
#pragma unroll
    for (int it = 0; it < 8; ++it) {
        int i = tid + it * 256;
        int r = i >> 5;
        int k = (i & 31) * 4;
        float4 av = make_float4(0.f, 0.f, 0.f, 0.f);
        int row = row0 + r;
        if (row < N) av = *(const float4*)(A + (size_t)row * HC + k);
        if (gelu) {
            av.x = gelu_exact(av.x); av.y = gelu_exact(av.y);
            av.z = gelu_exact(av.z); av.w = gelu_exact(av.w);
        }
        __nv_bfloat162 h01 = __float22bfloat162_rn(make_float2(av.x, av.y));
        __nv_bfloat162 h23 = __float22bfloat162_rn(make_float2(av.z, av.w));
        uint32_t off = (uint32_t)(r * WROW + k) * 2;
        *(uint2*)(smem + SM_A + off) = make_uint2(*(uint32_t*)&h01, *(uint32_t*)&h23);
    }
}

// bf16 A convert: 8 cols/thread, 16B loads/stores, 4 iterations
__device__ __forceinline__ void convert_A64_bf16(const __nv_bfloat16* __restrict__ A,
                                                 int row0, int N, char* smem, int tid, int gelu) {
#pragma unroll
    for (int it = 0; it < 4; ++it) {
        int i = tid + it * 256;
        int r = i >> 4;
        int k = (i & 15) * 8;
        int row = row0 + r;
        uint4 raw = make_uint4(0u, 0u, 0u, 0u);
        if (row < N) raw = *(const uint4*)(A + (size_t)row * HC + k);
        if (gelu) {
            float2 a0 = __bfloat1622float2(*(__nv_bfloat162*)&raw.x);
            float2 a1 = __bfloat1622float2(*(__nv_bfloat162*)&raw.y);
            float2 a2 = __bfloat1622float2(*(__nv_bfloat162*)&raw.z);
            float2 a3 = __bfloat1622float2(*(__nv_bfloat162*)&raw.w);
            a0.x = gelu_exact(a0.x); a0.y = gelu_exact(a0.y);
            a1.x = gelu_exact(a1.x); a1.y = gelu_exact(a1.y);
            a2.x = gelu_exact(a2.x); a2.y = gelu_exact(a2.y);
            a3.x = gelu_exact(a3.x); a3.y = gelu_exact(a3.y);
            __nv_bfloat162 h0 = __float22bfloat162_rn(a0);
            __nv_bfloat162 h1 = __float22bfloat162_rn(a1);
            __nv_bfloat162 h2 = __float22bfloat162_rn(a2);
            __nv_bfloat162 h3 = __float22bfloat162_rn(a3);
            raw = make_uint4(*(uint32_t*)&h0, *(uint32_t*)&h1,
                             *(uint32_t*)&h2, *(uint32_t*)&h3);
        }
        uint32_t off = (uint32_t)(r * WROW + k) * 2;
        *(uint4*)(smem + SM_A + off) = raw;
    }
}

// load one 34816-B W image asynchronously (2176 float4)
__device__ __forceinline__ void load_W_async(uint32_t sdst, const __nv_bfloat16* Wimg, int tid) {
#pragma unroll
    for (int j = 0; j < 9; j++) {
        int i = tid + j * 256;
        if (i < 2176) cp_async16(sdst + i * 16, (const float4*)Wimg + i);
    }
    asm volatile("cp.async.commit_group;" ::: "memory");
}

// 1-pass bf16 GEMM
__device__ __forceinline__ void mma_tile1(uint32_t a_lane, uint32_t b_lane, float acc[2][4][4]) {
#pragma unroll
    for (int i = 0; i < 2; i++)
#pragma unroll
        for (int j = 0; j < 4; j++)
#pragma unroll
            for (int q = 0; q < 4; q++) acc[i][j][q] = 0.f;
#pragma unroll
    for (int ks = 0; ks < 8; ks++) {
        uint32_t ar[2][4], br[2][4];
        ldm_x4(ar[0], a_lane + ks * 32);
        ldm_x4(ar[1], a_lane + ks * 32 + 16 * WROW * 2);
        ldm_x4(br[0], b_lane + ks * 32);
        ldm_x4(br[1], b_lane + ks * 32 + 16 * WROW * 2);
#pragma unroll
        for (int mt = 0; mt < 2; mt++) {
            mma16816(acc[mt][0], ar[mt], br[0] + 0);
            mma16816(acc[mt][1], ar[mt], br[0] + 2);
            mma16816(acc[mt][2], ar[mt], br[1] + 0);
            mma16816(acc[mt][3], ar[mt], br[1] + 2);
        }
    }
}

// ---------------- mega-chain GEMM kernel (1..6 steps, double-buffered W) -----
struct ChainP {
    const void* A;
    const float* xprev;
    const __nv_bfloat16* W[MAXSTEP];
    const float* bias[MAXSTEP];
    void* Cg[MAXSTEP];
    const float* gate[MAXSTEP];
    int relu[MAXSTEP];
    int half_out[MAXSTEP];
    int chain[MAXSTEP];
    int gelu_in;
    int nsteps;
    int N;
};

template <int ABF16>
__global__ void __launch_bounds__(256, 2)
chain_kernel(ChainP P) {
    extern __shared__ char smem[];
    int tid = threadIdx.x;
    int wid = tid >> 5;
    int lane = tid & 31;
    int row0 = blockIdx.x * 64;
    uint32_t sb = smem_u32(smem);

    load_W_async(sb + SM_W0, P.W[0], tid);
    if (ABF16)
        convert_A64_bf16((const __nv_bfloat16*)P.A, row0, P.N, smem, tid, P.gelu_in);
    else
        convert_A64_f32((const float*)P.A, row0, P.N, smem, tid, P.gelu_in);
    asm volatile("cp.async.wait_group 0;" ::: "memory");
    __syncthreads();
    if (P.nsteps > 1) load_W_async(sb + SM_W1, P.W[1], tid);

    int warpM = wid >> 2;
    int warpN = wid & 3;
    uint32_t a_lane = sb + SM_A +
        ((uint32_t)((warpM * 32 + (lane & 15)) * WROW + ((lane >> 4) << 3)) << 1);
    uint32_t b_lane0 = sb + SM_W0 +
        ((uint32_t)((warpN * 32 + (lane & 7) + ((lane >> 4) << 3)) * WROW +
                    (((lane >> 3) & 1) << 3)) << 1);
    int gid = lane >> 2, tq = lane & 3;

    for (int s = 0; s < P.nsteps; s++) {
        float acc[2][4][4];
        mma_tile1(a_lane, b_lane0 + (uint32_t)(s & 1) * WIMG_BYTES, acc);
        bool last = (s + 1 == P.nsteps);
        __syncthreads();                 // all warps done reading W[s] and A
        bool more2 = (s + 2 < P.nsteps);
        if (more2) load_W_async(sb + SM_W0 + (uint32_t)(s & 1) * WIMG_BYTES, P.W[s + 2], tid);

        const float* bias = P.bias[s];
        void* Cg = P.Cg[s];
        const float* gp = P.gate[s];
        int rl = P.relu[s];
        int ho = P.half_out[s];
        int ch = P.chain[s];
        float g = 0.f, og = 0.f;
        if (gp) { g = 1.f / (1.f + expf(-*gp)); og = 1.f - g; }
#pragma unroll
        for (int mt = 0; mt < 2; mt++) {
#pragma unroll
            for (int nt = 0; nt < 4; nt++) {
                int col = warpN * 32 + nt * 8 + tq * 2;
                float2 bv = *(const float2*)(bias + col);
#pragma unroll
                for (int half = 0; half < 2; half++) {
                    int rloc = warpM * 32 + mt * 16 + gid + half * 8;
                    int row = row0 + rloc;
                    float c0 = acc[mt][nt][half * 2 + 0] + bv.x;
                    float c1 = acc[mt][nt][half * 2 + 1] + bv.y;
                    if (rl) { c0 = fmaxf(c0, 0.f); c1 = fmaxf(c1, 0.f); }
                    if (gp && row < P.N) {
                        float2 xp = *(const float2*)(P.xprev + (size_t)row * HC + col);
                        c0 = g * c0 + og * xp.x;
                        c1 = g * c1 + og * xp.y;
                    }
                    if (Cg && row < P.N) {
                        if (ho) {
                            __nv_bfloat162 h2 = __float22bfloat162_rn(make_float2(c0, c1));
                            *(uint32_t*)((__nv_bfloat16*)Cg + (size_t)row * HC + col) =
                                *(uint32_t*)&h2;
                        } else {
                            *(float2*)((float*)Cg + (size_t)row * HC + col) =
                                make_float2(c0, c1);
                        }
                    }
                    if (ch) {
                        __nv_bfloat162 h2 = __float22bfloat162_rn(make_float2(c0, c1));
                        uint32_t off = (uint32_t)(rloc * WROW + col) * 2;
                        *(uint32_t*)(smem + SM_A + off) = *(uint32_t*)&h2;
                    }
                }
            }
        }
        if (!last) {
            if (more2)
                asm volatile("cp.async.wait_group 1;" ::: "memory");  // W[s+1] done
            else
                asm volatile("cp.async.wait_group 0;" ::: "memory");
            __syncthreads();             // W[s+1] + chained A stores visible
        }
    }
}

// ---------------- CSR build ----------------
__global__ void clear_cnt_kernel(int* c0, int n0, int* c1, int n1,
                                 float* gsum, float* gcnt) {
    int i = blockIdx.x * blockDim.x + threadIdx.x;
    if (i < n0) c0[i] = 0;
    if (i < n1) c1[i] = 0;
    if (i < NG * 2) gsum[i] = 0.f;
    if (i < NG) gcnt[i] = 0.f;
}

__global__ void hist_kernel(const int* d0, int E0, int* c0,
                            const int* d1, int E1, int* c1) {
    int e = blockIdx.x * blockDim.x + threadIdx.x;
    if (e < E0) atomicAdd(&c0[d0[e]], 1);
    if (e < E1) atomicAdd(&c1[d1[e]], 1);
}

__global__ void scan_p1_kernel(const int* c0, int n0, int* rp0, int* of0, int* bs0,
                               const int* c1, int n1, int* rp1, int* of1, int* bs1) {
    int seg = blockIdx.y;
    const int* cnt = seg ? c1 : c0;
    int n = seg ? n1 : n0;
    int* rp = seg ? rp1 : rp0;
    int* of = seg ? of1 : of0;
    int* bs = seg ? bs1 : bs0;
    int tid = threadIdx.x;
    int i = blockIdx.x * 1024 + tid;
    int v = (i < n) ? cnt[i] : 0;
    int lane = tid & 31, wd = tid >> 5;
    int x = v;
#pragma unroll
    for (int off = 1; off < 32; off <<= 1) {
        int t = __shfl_up_sync(0xffffffffu, x, off);
        if (lane >= off) x += t;
    }
    __shared__ int ws[32];
    if (lane == 31) ws[wd] = x;
    __syncthreads();
    if (wd == 0) {
        int w = ws[lane];
#pragma unroll
        for (int off = 1; off < 32; off <<= 1) {
            int t = __shfl_up_sync(0xffffffffu, w, off);
            if (lane >= off) w += t;
        }
        ws[lane] = w;
    }
    __syncthreads();
    int incl = x + (wd > 0 ? ws[wd - 1] : 0);
    if (i < n) { rp[i + 1] = incl; of[i + 1] = incl; }
    if (tid == 1023) bs[blockIdx.x] = incl;
    if (i == 0) { rp[0] = 0; of[0] = 0; }
}

__global__ void scan_p2_kernel(int* rp0, int* of0, const int* bs0, int n0,
                               int* rp1, int* of1, const int* bs1, int n1) {
    int seg = blockIdx.y;
    int* rp = seg ? rp1 : rp0;
    int* of = seg ? of1 : of0;
    const int* bs = seg ? bs1 : bs0;
    int n = seg ? n1 : n0;
    int bid = blockIdx.x;
    if (bid == 0) return;
    __shared__ int soff;
    if (threadIdx.x < 32) {
        int acc = 0;
        for (int j = threadIdx.x; j < bid; j += 32) acc += bs[j];
#pragma unroll
        for (int o = 16; o; o >>= 1) acc += __shfl_xor_sync(0xffffffffu, acc, o);
        if (threadIdx.x == 0) soff = acc;
    }
    __syncthreads();
    int i = bid * 1024 + threadIdx.x;
    if (i < n) { rp[i + 1] += soff; of[i + 1] += soff; }
}

__global__ void scatter_kernel(const int* s0, const int* d0, int E0, int* o0, int* ss0,
                               const int* s1, const int* d1, int E1, int* o1, int* ss1) {
    int e = blockIdx.x * blockDim.x + threadIdx.x;
    if (e < E0) { int p = atomicAdd(&o0[d0[e]], 1); ss0[p] = s0[e]; }
    if (e < E1) { int p = atomicAdd(&o1[d1[e]], 1); ss1[p] = s1[e]; }
}

// ---------------- CSR attention: warp per dst, all-bf16, 2-edge unroll -------
struct CsrP {
    const __nv_bfloat16* q[2];
    const __nv_bfloat16* kt[2];
    const __nv_bfloat16* vt[2];
    const int* rowptr[2];
    const int* ssrc[2];
    const float* prel[2];
    __nv_bfloat16* agg[2];
    int Nd0, Ndtot;
};

__global__ void attn_csr_kernel(CsrP P) {
    int w = blockIdx.x * 8 + (threadIdx.x >> 5);
    if (w >= P.Ndtot) return;
    int seg = w >= P.Nd0;
    int d = w - (seg ? P.Nd0 : 0);
    int lane = threadIdx.x & 31;
    int h = lane >> 3;
    const int* rp = P.rowptr[seg];
    int beg = rp[d], end = rp[d + 1];
    float pr = P.prel[seg][h] * 0.17677669529663687f;
    float4 qv;
    {
        uint2 qraw = *(const uint2*)(P.q[seg] + (size_t)d * HC + lane * 4);
        float2 qa = __bfloat1622float2(*(__nv_bfloat162*)&qraw.x);
        float2 qb = __bfloat1622float2(*(__nv_bfloat162*)&qraw.y);
        qv = make_float4(qa.x, qa.y, qb.x, qb.y);
    }
    const __nv_bfloat16* kt = P.kt[seg];
    const __nv_bfloat16* vt = P.vt[seg];
    const int* ss = P.ssrc[seg];
    float4 acc = make_float4(0.f, 0.f, 0.f, 0.f);
    float den = 0.f;
    int i = beg;
    for (; i + 1 < end; i += 2) {
        int s0 = ss[i], s1 = ss[i + 1];
        uint2 k0 = *(const uint2*)(kt + (size_t)s0 * HC + lane * 4);
        uint2 v0 = *(const uint2*)(vt + (size_t)s0 * HC + lane * 4);
        uint2 k1 = *(const uint2*)(kt + (size_t)s1 * HC + lane * 4);
        uint2 v1 = *(const uint2*)(vt + (size_t)s1 * HC + lane * 4);
        float2 k0a = __bfloat1622float2(*(__nv_bfloat162*)&k0.x);
        float2 k0b = __bfloat1622float2(*(__nv_bfloat162*)&k0.y);
        float2 k1a = __bfloat1622float2(*(__nv_bfloat162*)&k1.x);
        float2 k1b = __bfloat1622float2(*(__nv_bfloat162*)&k1.y);
        float p0 = qv.x * k0a.x + qv.y * k0a.y + qv.z * k0b.x + qv.w * k0b.y;
        float p1 = qv.x * k1a.x + qv.y * k1a.y + qv.z * k1b.x + qv.w * k1b.y;
        p0 += __shfl_xor_sync(0xffffffffu, p0, 1);
        p1 += __shfl_xor_sync(0xffffffffu, p1, 1);
        p0 += __shfl_xor_sync(0xffffffffu, p0, 2);
        p1 += __shfl_xor_sync(0xffffffffu, p1, 2);
        p0 += __shfl_xor_sync(0xffffffffu, p0, 4);
        p1 += __shfl_xor_sync(0xffffffffu, p1, 4);
        float ex0 = expf(p0 * pr);
        float ex1 = expf(p1 * pr);
        den += ex0;
        den += ex1;
        float2 v0a = __bfloat1622float2(*(__nv_bfloat162*)&v0.x);
        float2 v0b = __bfloat1622float2(*(__nv_bfloat162*)&v0.y);
        float2 v1a = __bfloat1622float2(*(__nv_bfloat162*)&v1.x);
        float2 v1b = __bfloat1622float2(*(__nv_bfloat162*)&v1.y);
        acc.x += ex0 * v0a.x + ex1 * v1a.x;
        acc.y += ex0 * v0a.y + ex1 * v1a.y;
        acc.z += ex0 * v0b.x + ex1 * v1b.x;
        acc.w += ex0 * v0b.y + ex1 * v1b.y;
    }
    if (i < end) {
        int s = ss[i];
        uint2 kraw = *(const uint2*)(kt + (size_t)s * HC + lane * 4);
        uint2 vraw = *(const uint2*)(vt + (size_t)s * HC + lane * 4);
        float2 ka = __bfloat1622float2(*(__nv_bfloat162*)&kraw.x);
        float2 kb = __bfloat1622float2(*(__nv_bfloat162*)&kraw.y);
        float2 va = __bfloat1622float2(*(__nv_bfloat162*)&vraw.x);
        float2 vb = __bfloat1622float2(*(__nv_bfloat162*)&vraw.y);
        float p = qv.x * ka.x + qv.y * ka.y + qv.z * kb.x + qv.w * kb.y;
        p += __shfl_xor_sync(0xffffffffu, p, 1);
        p += __shfl_xor_sync(0xffffffffu, p, 2);
        p += __shfl_xor_sync(0xffffffffu, p, 4);
        float ex = expf(p * pr);
        den += ex;
        acc.x += ex * va.x; acc.y += ex * va.y;
        acc.z += ex * vb.x; acc.w += ex * vb.y;
    }
    float rcp = (den > 0.f) ? 1.f / den : 0.f;
    __nv_bfloat162 o01 = __float22bfloat162_rn(make_float2(acc.x * rcp, acc.y * rcp));
    __nv_bfloat162 o23 = __float22bfloat162_rn(make_float2(acc.z * rcp, acc.w * rcp));
    *(uint2*)(P.agg[seg] + (size_t)d * HC + lane * 4) =
        make_uint2(*(uint32_t*)&o01, *(uint32_t*)&o23);
}

// ---------------- output head ----------------
__global__ void out_head_kernel(const float* __restrict__ X, const float* __restrict__ W2,
                                const float* __restrict__ b2, const int* __restrict__ batch,
                                float* __restrict__ gsum, float* __restrict__ gcnt, int N) {
    int n = blockIdx.x * 8 + (threadIdx.x >> 5);
    if (n >= N) return;
    int lane = threadIdx.x & 31;
    float4 x = *(const float4*)(X + (size_t)n * HC + lane * 4);
    float4 wa = *(const float4*)(W2 + lane * 8);
    float4 wb = *(const float4*)(W2 + lane * 8 + 4);
    float p0 = x.x * wa.x + x.y * wa.z + x.z * wb.x + x.w * wb.z;
    float p1 = x.x * wa.y + x.y * wa.w + x.z * wb.y + x.w * wb.w;
#pragma unroll
    for (int off = 16; off > 0; off >>= 1) {
        p0 += __shfl_xor_sync(0xffffffffu, p0, off);
        p1 += __shfl_xor_sync(0xffffffffu, p1, off);
    }
    if (lane == 0) {
        float l0 = p0 + b2[0], l1 = p1 + b2[1];
        float m = fmaxf(l0, l1);
        float e0 = expf(l0 - m), e1 = expf(l1 - m);
        float inv = 1.f / (e0 + e1);
        int g = batch[n];
        atomicAdd(&gsum[g * 2 + 0], e0 * inv);
        atomicAdd(&gsum[g * 2 + 1], e1 * inv);
        atomicAdd(&gcnt[g], 1.f);
    }
}

__global__ void finalize_kernel(const float* __restrict__ gsum, const float* __restrict__ gcnt,
                                float* __restrict__ out, int G) {
    int g = blockIdx.x * blockDim.x + threadIdx.x;
    if (g >= G) return;
    float c = fmaxf(gcnt[g], 1.f);
    out[g * 2 + 0] = gsum[g * 2 + 0] / c;
    out[g * 2 + 1] = gsum[g * 2 + 1] / c;
}

// ---------------- host orchestration ----------------
extern "C" void kernel_launch(void* const* d_in, const int* in_sizes, int n_in,
                              void* d_out, int out_size) {
    const float* x_var = (const float*)d_in[0];
    const float* x_con = (const float*)d_in[1];
    const float* mlp_in_w = (const float*)d_in[2];
    const float* mlp_in_b = (const float*)d_in[3];
    const float* w0 = (const float*)d_in[4];
    const float* b0 = (const float*)d_in[5];
    const float* w1 = (const float*)d_in[6];
    const float* b1 = (const float*)d_in[7];
    const float* w2 = (const float*)d_in[8];
    const float* b2 = (const float*)d_in[9];
    const float* k_w = (const float*)d_in[10];
    const float* k_b = (const float*)d_in[11];
    const float* q_w = (const float*)d_in[12];
    const float* q_b = (const float*)d_in[13];
    const float* v_w = (const float*)d_in[14];
    const float* v_b = (const float*)d_in[15];
    const float* a_w = (const float*)d_in[16];
    const float* a_b = (const float*)d_in[17];
    const float* skip = (const float*)d_in[18];
    const float* a_rel = (const float*)d_in[19];
    const float* m_rel = (const float*)d_in[20];
    const float* p_rel = (const float*)d_in[21];
    const int* evc = (const int*)d_in[22];
    const int* ecv = (const int*)d_in[23];
    const int* batch = (const int*)d_in[24];
    float* out = (float*)d_out;

    int Nv = in_sizes[0] / HC;
    int Nc = in_sizes[1] / HC;
    int Evc = in_sizes[22] / 2;
    int Ecv = in_sizes[23] / 2;

    float *xs0, *xs1, *tmp, *bcomp, *gsum, *gcnt;
    __nv_bfloat16 *kt0, *vt0, *kt1, *vt1, *qe0, *qe1, *aggv, *aggc;
    int *cnt0, *cnt1, *rp0, *rp1, *of0, *of1, *ss0, *ss1, *bs0, *bs1;
    __nv_bfloat16* wimg;
    cudaGetSymbolAddress((void**)&xs0, g_xs0);
    cudaGetSymbolAddress((void**)&xs1, g_xs1);
    cudaGetSymbolAddress((void**)&tmp, g_tmp);
    cudaGetSymbolAddress((void**)&kt0, g_kt0);
    cudaGetSymbolAddress((void**)&vt0, g_vt0);
    cudaGetSymbolAddress((void**)&kt1, g_kt1);
    cudaGetSymbolAddress((void**)&vt1, g_vt1);
    cudaGetSymbolAddress((void**)&qe0, g_qe0);
    cudaGetSymbolAddress((void**)&qe1, g_qe1);
    cudaGetSymbolAddress((void**)&aggv, g_aggv);
    cudaGetSymbolAddress((void**)&aggc, g_aggc);
    cudaGetSymbolAddress((void**)&wimg, g_wimg);
    cudaGetSymbolAddress((void**)&bcomp, g_bcomp);
    cudaGetSymbolAddress((void**)&gsum, g_gsum);
    cudaGetSymbolAddress((void**)&gcnt, g_gcnt);
    cudaGetSymbolAddress((void**)&cnt0, g_cnt0);
    cudaGetSymbolAddress((void**)&cnt1, g_cnt1);
    cudaGetSymbolAddress((void**)&rp0, g_rp0);
    cudaGetSymbolAddress((void**)&rp1, g_rp1);
    cudaGetSymbolAddress((void**)&of0, g_of0);
    cudaGetSymbolAddress((void**)&of1, g_of1);
    cudaGetSymbolAddress((void**)&ss0, g_ss0);
    cudaGetSymbolAddress((void**)&ss1, g_ss1);
    cudaGetSymbolAddress((void**)&bs0, g_bs0);
    cudaGetSymbolAddress((void**)&bs1, g_bs1);

    cudaFuncSetAttribute(chain_kernel<0>, cudaFuncAttributeMaxDynamicSharedMemorySize, SMEM_MM);
    cudaFuncSetAttribute(chain_kernel<1>, cudaFuncAttributeMaxDynamicSharedMemorySize, SMEM_MM);

    // ---- weight packing ----
    PackJobs pj;
    for (int j = 0; j < NW; j++) { pj.w[j] = nullptr; pj.rel[j] = nullptr; pj.bin[j] = nullptr; pj.bout[j] = nullptr; }
    for (int t = 0; t < 2; t++)
        for (int i = 0; i < 3; i++) pj.w[t * 3 + i] = mlp_in_w + (size_t)(t * 3 + i) * 16384;
    for (int li = 0; li < 4; li++) {
        pj.w[6 + li] = k_w + (size_t)li * 16384;
        pj.rel[6 + li] = a_rel + (size_t)li * 4096;
        pj.bin[6 + li] = k_b + (size_t)li * 128;
        pj.bout[6 + li] = bcomp + (size_t)li * 128;
        pj.w[10 + li] = v_w + (size_t)li * 16384;
        pj.rel[10 + li] = m_rel + (size_t)li * 4096;
        pj.bin[10 + li] = v_b + (size_t)li * 128;
        pj.bout[10 + li] = bcomp + (size_t)(4 + li) * 128;
        pj.w[14 + li] = q_w + (size_t)li * 16384;
        pj.w[18 + li] = a_w + (size_t)li * 16384;
    }
    pj.w[22] = w0;
    pj.w[23] = w1;
    pack_kernel<<<dim3(NW, 4), 256>>>(pj, wimg);

#define IMG(j) (wimg + (size_t)(j) * WIMG_ELEMS)

    // ---- CSR build + head clear (seg0: dst=con, seg1: dst=var) ----
    {
        int mx = (Nv > Nc ? Nv : Nc);
        clear_cnt_kernel<<<(mx + 511) / 512, 512>>>(cnt0, Nc, cnt1, Nv, gsum, gcnt);
        int me = (Evc > Ecv ? Evc : Ecv);
        hist_kernel<<<(me + 511) / 512, 512>>>(evc + Evc, Evc, cnt0, ecv + Ecv, Ecv, cnt1);
        int nb = (mx + 1023) / 1024;
        scan_p1_kernel<<<dim3(nb, 2), 1024>>>(cnt0, Nc, rp0, of0, bs0,
                                              cnt1, Nv, rp1, of1, bs1);
        scan_p2_kernel<<<dim3(nb, 2), 1024>>>(rp0, of0, bs0, Nc, rp1, of1, bs1, Nv);
        scatter_kernel<<<(me + 511) / 512, 512>>>(evc, evc + Evc, Evc, of0, ss0,
                                                  ecv, ecv + Ecv, Ecv, of1, ss1);
    }

    auto set_kvq = [&](ChainP& c, int s0, int t, int li) {
        c.W[s0 + 0] = IMG(6 + li);  c.bias[s0 + 0] = bcomp + (size_t)li * 128;
        c.Cg[s0 + 0] = (t == 0) ? (void*)kt0 : (void*)kt1;
        c.half_out[s0 + 0] = 1;
        c.W[s0 + 1] = IMG(10 + li); c.bias[s0 + 1] = bcomp + (size_t)(4 + li) * 128;
        c.Cg[s0 + 1] = (t == 0) ? (void*)vt0 : (void*)vt1;
        c.half_out[s0 + 1] = 1;
        c.W[s0 + 2] = IMG(14 + li); c.bias[s0 + 2] = q_b + (size_t)li * 128;
        c.Cg[s0 + 2] = (t == 0) ? (void*)qe1 : (void*)qe0;
        c.half_out[s0 + 2] = 1;
    };

    // ---- mega chain per type: input MLP x3 -> xs -> K,V,Q (layer 0) ----
    for (int t = 0; t < 2; t++) {
        ChainP c{};
        c.A = (t == 0) ? (const void*)x_var : (const void*)x_con;
        c.N = (t == 0) ? Nv : Nc;
        c.xprev = nullptr;
        c.gelu_in = 0;
        c.nsteps = 6;
        for (int i = 0; i < 3; i++) {
            c.W[i] = IMG(t * 3 + i);
            c.bias[i] = mlp_in_b + (size_t)(t * 3 + i) * 128;
            c.relu[i] = (i < 2);
            c.chain[i] = 1;
        }
        c.Cg[2] = (t == 0) ? (void*)xs0 : (void*)xs1;
        set_kvq(c, 3, t, t);
        chain_kernel<0><<<(c.N + 63) / 64, 256, SMEM_MM>>>(c);
    }

    // ---- layer 0 attention ----
    {
        CsrP cp{};
        cp.q[0] = qe0; cp.kt[0] = kt0; cp.vt[0] = vt0;
        cp.rowptr[0] = rp0; cp.ssrc[0] = ss0;
        cp.prel[0] = p_rel + 0 * 4;
        cp.agg[0] = aggc;
        cp.q[1] = qe1; cp.kt[1] = kt1; cp.vt[1] = vt1;
        cp.rowptr[1] = rp1; cp.ssrc[1] = ss1;
        cp.prel[1] = p_rel + 1 * 4;
        cp.agg[1] = aggv;
        cp.Nd0 = Nc; cp.Ndtot = Nc + Nv;
        attn_csr_kernel<<<(cp.Ndtot + 7) / 8, 256>>>(cp);
    }

    // ---- per type: gated(layer0) -> xs -> K,V,Q (layer 1) ----
    for (int t = 0; t < 2; t++) {
        int li = 0 * 2 + t;
        ChainP c{};
        c.A = (t == 0) ? (const void*)aggv : (const void*)aggc;
        c.N = (t == 0) ? Nv : Nc;
        c.xprev = (t == 0) ? xs0 : xs1;
        c.gelu_in = 1;
        c.nsteps = 4;
        c.W[0] = IMG(18 + li); c.bias[0] = a_b + (size_t)li * 128;
        c.gate[0] = skip + li;
        c.Cg[0] = (t == 0) ? (void*)xs0 : (void*)xs1;
        c.chain[0] = 1;
        set_kvq(c, 1, t, 2 + t);
        chain_kernel<1><<<(c.N + 63) / 64, 256, SMEM_MM>>>(c);
    }

    // ---- layer 1 attention ----
    {
        CsrP cp{};
        cp.q[0] = qe0; cp.kt[0] = kt0; cp.vt[0] = vt0;
        cp.rowptr[0] = rp0; cp.ssrc[0] = ss0;
        cp.prel[0] = p_rel + 2 * 4;
        cp.agg[0] = aggc;
        cp.q[1] = qe1; cp.kt[1] = kt1; cp.vt[1] = vt1;
        cp.rowptr[1] = rp1; cp.ssrc[1] = ss1;
        cp.prel[1] = p_rel + 3 * 4;
        cp.agg[1] = aggv;
        cp.Nd0 = Nc; cp.Ndtot = Nc + Nv;
        attn_csr_kernel<<<(cp.Ndtot + 7) / 8, 256>>>(cp);
    }

    // ---- var: gated(layer1) -> xs0 -> head W0 -> head W1 -> tmp ----
    {
        ChainP c{};
        c.A = (const void*)aggv;
        c.N = Nv;
        c.xprev = xs0;
        c.gelu_in = 1;
        c.nsteps = 3;
        c.W[0] = IMG(18 + 2); c.bias[0] = a_b + (size_t)2 * 128;
        c.gate[0] = skip + 2;
        c.Cg[0] = (void*)xs0;
        c.chain[0] = 1;
        c.W[1] = IMG(22); c.bias[1] = b0; c.relu[1] = 1; c.chain[1] = 1;
        c.W[2] = IMG(23); c.bias[2] = b1; c.relu[2] = 1; c.Cg[2] = (void*)tmp;
        chain_kernel<1><<<(Nv + 63) / 64, 256, SMEM_MM>>>(c);
    }
    // ---- con: gated(layer1) -> xs1 (1 step) ----
    {
        ChainP c{};
        c.A = (const void*)aggc;
        c.N = Nc;
        c.xprev = xs1;
        c.gelu_in = 1;
        c.nsteps = 1;
        c.W[0] = IMG(18 + 3); c.bias[0] = a_b + (size_t)3 * 128;
        c.gate[0] = skip + 3;
        c.Cg[0] = (void*)xs1;
        chain_kernel<1><<<(Nc + 63) / 64, 256, SMEM_MM>>>(c);
    }

    out_head_kernel<<<(Nv + 7) / 8, 256>>>(tmp, w2, b2, batch, gsum, gcnt, Nv);
    finalize_kernel<<<(NG + 255) / 256, 256>>>(gsum, gcnt, out, NG);
}